// round 2
// baseline (speedup 1.0000x reference)
#include <cuda_runtime.h>

#define D_MODEL 1024
#define NHEAD   16
#define DHEAD   64
#define DFF_SZ  4096
#define BATCH   2
#define SEQ     2048
#define MROWS   (BATCH*SEQ)   // 4096

// ---------------- scratch (device globals; no allocations allowed) ----------
__device__ float g_q  [(size_t)MROWS * D_MODEL];
__device__ float g_k  [(size_t)MROWS * D_MODEL];
__device__ float g_v  [(size_t)MROWS * D_MODEL];
__device__ float g_ctx[(size_t)MROWS * D_MODEL];
__device__ float g_tmp[(size_t)MROWS * D_MODEL];
__device__ float g_x1 [(size_t)MROWS * D_MODEL];
__device__ float g_x2 [(size_t)MROWS * D_MODEL];
__device__ float g_ff [(size_t)MROWS * DFF_SZ];

// ---------------- packed fp32x2 helpers (Blackwell FFMA2 path) --------------
__device__ __forceinline__ unsigned long long pk2(float lo, float hi) {
    unsigned long long r;
    asm("mov.b64 %0, {%1,%2};" : "=l"(r) : "f"(lo), "f"(hi));
    return r;
}
__device__ __forceinline__ void upk2(unsigned long long v, float& lo, float& hi) {
    asm("mov.b64 {%0,%1}, %2;" : "=f"(lo), "=f"(hi) : "l"(v));
}
__device__ __forceinline__ void fma2(unsigned long long& d,
                                     unsigned long long a, unsigned long long b) {
    asm("fma.rn.f32x2 %0, %1, %2, %0;" : "+l"(d) : "l"(a), "l"(b));
}
__device__ __forceinline__ void mul2(unsigned long long& d, unsigned long long a) {
    asm("mul.rn.f32x2 %0, %0, %1;" : "+l"(d) : "l"(a));
}

// ---------------- SGEMM: C[M,N] = A[M,K] @ W[N,K]^T + bias, optional ReLU ----
// 128x128 tile, 256 threads, 8x8 per-thread micro-tile, FFMA2 inner product.
template<bool RELU>
__global__ void __launch_bounds__(256, 2) sgemm_bias(
    const float* __restrict__ A, const float* __restrict__ W,
    const float* __restrict__ bias, float* __restrict__ C,
    int M, int N, int K)
{
    __shared__ float As[16 * 132];
    __shared__ float Bs[16 * 132];

    const int t  = threadIdx.x;
    const int lr = t >> 2;            // 0..63
    const int lc = (t & 3) << 2;      // 0,4,8,12
    const int ty = t >> 4;            // 0..15
    const int tx = t & 15;            // 0..15

    const float* Ab = A + ((size_t)blockIdx.y * 128 + lr) * K + lc;
    const float* Wb = W + ((size_t)blockIdx.x * 128 + lr) * K + lc;

    unsigned long long acc2[4][8];    // row-pairs (8 rows) x 8 cols
#pragma unroll
    for (int ip = 0; ip < 4; ip++)
#pragma unroll
        for (int j = 0; j < 8; j++) acc2[ip][j] = 0ULL;

    for (int k0 = 0; k0 < K; k0 += 16) {
        float4 a0 = *(const float4*)(Ab + k0);
        float4 a1 = *(const float4*)(Ab + (size_t)64 * K + k0);
        float4 w0 = *(const float4*)(Wb + k0);
        float4 w1 = *(const float4*)(Wb + (size_t)64 * K + k0);
        __syncthreads();
        As[(lc + 0) * 132 + lr]      = a0.x;
        As[(lc + 1) * 132 + lr]      = a0.y;
        As[(lc + 2) * 132 + lr]      = a0.z;
        As[(lc + 3) * 132 + lr]      = a0.w;
        As[(lc + 0) * 132 + lr + 64] = a1.x;
        As[(lc + 1) * 132 + lr + 64] = a1.y;
        As[(lc + 2) * 132 + lr + 64] = a1.z;
        As[(lc + 3) * 132 + lr + 64] = a1.w;
        Bs[(lc + 0) * 132 + lr]      = w0.x;
        Bs[(lc + 1) * 132 + lr]      = w0.y;
        Bs[(lc + 2) * 132 + lr]      = w0.z;
        Bs[(lc + 3) * 132 + lr]      = w0.w;
        Bs[(lc + 0) * 132 + lr + 64] = w1.x;
        Bs[(lc + 1) * 132 + lr + 64] = w1.y;
        Bs[(lc + 2) * 132 + lr + 64] = w1.z;
        Bs[(lc + 3) * 132 + lr + 64] = w1.w;
        __syncthreads();

#pragma unroll
        for (int kk = 0; kk < 16; kk++) {
            unsigned long long a2[4];
#pragma unroll
            for (int ip = 0; ip < 4; ip++)
                a2[ip] = *(const unsigned long long*)&As[kk * 132 + ty * 8 + 2 * ip];
            float4 rb0 = *(const float4*)&Bs[kk * 132 + tx * 8];
            float4 rb1 = *(const float4*)&Bs[kk * 132 + tx * 8 + 4];
            float rb[8] = {rb0.x, rb0.y, rb0.z, rb0.w, rb1.x, rb1.y, rb1.z, rb1.w};
            unsigned long long bd[8];
#pragma unroll
            for (int j = 0; j < 8; j++) bd[j] = pk2(rb[j], rb[j]);
#pragma unroll
            for (int ip = 0; ip < 4; ip++)
#pragma unroll
                for (int j = 0; j < 8; j++)
                    fma2(acc2[ip][j], a2[ip], bd[j]);
        }
    }

    const int row0 = blockIdx.y * 128 + ty * 8;
    const int col0 = blockIdx.x * 128 + tx * 8;
    float4 b0 = *(const float4*)(bias + col0);
    float4 b1 = *(const float4*)(bias + col0 + 4);
    float bb[8] = {b0.x, b0.y, b0.z, b0.w, b1.x, b1.y, b1.z, b1.w};
#pragma unroll
    for (int ip = 0; ip < 4; ip++) {
        float lo[8], hi[8];
#pragma unroll
        for (int j = 0; j < 8; j++) {
            upk2(acc2[ip][j], lo[j], hi[j]);
            lo[j] += bb[j];
            hi[j] += bb[j];
            if (RELU) { lo[j] = fmaxf(lo[j], 0.f); hi[j] = fmaxf(hi[j], 0.f); }
        }
        float* r0p = C + (size_t)(row0 + 2 * ip) * N + col0;
        float* r1p = C + (size_t)(row0 + 2 * ip + 1) * N + col0;
        *(float4*)(r0p)     = make_float4(lo[0], lo[1], lo[2], lo[3]);
        *(float4*)(r0p + 4) = make_float4(lo[4], lo[5], lo[6], lo[7]);
        *(float4*)(r1p)     = make_float4(hi[0], hi[1], hi[2], hi[3]);
        *(float4*)(r1p + 4) = make_float4(hi[4], hi[5], hi[6], hi[7]);
    }
}

// ---------------- Fused attention (flash-style, 128x64 tiles, DK=64) --------
// Q,K,V,O: [B*rows, D_MODEL], head h at column h*64. mask: [B, SEQ, Skv] int.
// causal=1: analytic tril mask, no mask reads, above-diagonal k-tiles skipped.
#define QTILE 128
#define KTILE 64
// smem floats: q_s 64*132, k_s 64*68, v_s 64*68, p_s 128*68
#define ATTN_SMEM_FLOATS (64*132 + 64*68 + 64*68 + 128*68)

__global__ void __launch_bounds__(256, 2) attn_kernel(
    const float* __restrict__ Q, const float* __restrict__ K,
    const float* __restrict__ V, const int* __restrict__ mask,
    float* __restrict__ O, int Skv, int causal)
{
    extern __shared__ float sm[];
    float* q_s = sm;                       // [64 d][132]: q_s[d*132 + r] (rows contiguous)
    float* k_s = sm + 64 * 132;            // [64 d][68]:  k_s[d*68 + c]
    float* v_s = k_s + 64 * 68;            // [64 kv][68]: v_s[kv*68 + d]
    float* p_s = v_s + 64 * 68;            // [128 r][68]: p_s[r*68 + kv]

    const int t  = threadIdx.x;
    const int ty = t >> 4;                 // 0..15 -> rows ty*8..+7
    const int tx = t & 15;                 // 0..15 -> cols tx*4..+3
    const int r0 = ty * 8;
    const int c0 = tx * 4;
    const int qt = causal ? (gridDim.x - 1 - blockIdx.x) : blockIdx.x; // heavy first
    const int h  = blockIdx.y;
    const int b  = blockIdx.z;
    const int qrow0 = qt * QTILE;

    const size_t qbase = ((size_t)(b * SEQ + qrow0)) * D_MODEL + h * DHEAD;

    // load Q tile transposed: 128 rows x 64 d
#pragma unroll
    for (int e = 0; e < 32; e++) {
        int lin = e * 256 + t;
        int r = lin >> 6, d = lin & 63;
        q_s[d * 132 + r] = Q[qbase + (size_t)r * D_MODEL + d];
    }

    float m_i[8], l_i[8], alpha[8];
    unsigned long long o2[4][4];
#pragma unroll
    for (int i = 0; i < 8; i++) { m_i[i] = -1e30f; l_i[i] = 0.f; }
#pragma unroll
    for (int ip = 0; ip < 4; ip++)
#pragma unroll
        for (int j = 0; j < 4; j++) o2[ip][j] = 0ULL;

    const int ntiles = causal ? (2 * qt + 2) : (Skv >> 6);

    for (int jt = 0; jt < ntiles; jt++) {
        __syncthreads();   // protect k_s/v_s/p_s against prior-iteration readers
        const size_t kbase = ((size_t)(b * Skv + jt * KTILE)) * D_MODEL + h * DHEAD;
#pragma unroll
        for (int e = 0; e < 16; e++) {
            int lin = e * 256 + t;
            int r = lin >> 6, d = lin & 63;
            float kvv = K[kbase + (size_t)r * D_MODEL + d];
            float vvv = V[kbase + (size_t)r * D_MODEL + d];
            k_s[d * 68 + r] = kvv;
            v_s[r * 68 + d] = vvv;
        }
        __syncthreads();

        // ---- S = Q K^T (row-pair packed FFMA2) ----
        unsigned long long s2[4][4];
#pragma unroll
        for (int ip = 0; ip < 4; ip++)
#pragma unroll
            for (int j = 0; j < 4; j++) s2[ip][j] = 0ULL;

#pragma unroll 4
        for (int d = 0; d < 64; d++) {
            unsigned long long a2[4];
#pragma unroll
            for (int ip = 0; ip < 4; ip++)
                a2[ip] = *(const unsigned long long*)&q_s[d * 132 + r0 + 2 * ip];
            float4 kb = *(const float4*)&k_s[d * 68 + c0];
            unsigned long long bd[4] = {pk2(kb.x, kb.x), pk2(kb.y, kb.y),
                                        pk2(kb.z, kb.z), pk2(kb.w, kb.w)};
#pragma unroll
            for (int ip = 0; ip < 4; ip++)
#pragma unroll
                for (int j = 0; j < 4; j++)
                    fma2(s2[ip][j], a2[ip], bd[j]);
        }

        // ---- scale + mask + online softmax (16-lane row reductions) ----
        const bool needc = causal && (jt >= 2 * qt);
#pragma unroll
        for (int ip = 0; ip < 4; ip++) {
            float sl[4], sh[4];
#pragma unroll
            for (int j = 0; j < 4; j++) upk2(s2[ip][j], sl[j], sh[j]);
#pragma unroll
            for (int half = 0; half < 2; half++) {
                float sv[4];
#pragma unroll
                for (int j = 0; j < 4; j++) sv[j] = half ? sh[j] : sl[j];
                const int i  = 2 * ip + half;
                const int qg = qrow0 + r0 + i;
                if (causal) {
                    if (needc) {
#pragma unroll
                        for (int j = 0; j < 4; j++) {
                            int cj = jt * KTILE + c0 + j;
                            sv[j] = (cj <= qg) ? sv[j] * 0.125f : -1e9f;
                        }
                    } else {
#pragma unroll
                        for (int j = 0; j < 4; j++) sv[j] *= 0.125f;
                    }
                } else {
                    int4 mv = *(const int4*)(mask + ((size_t)b * SEQ + qg) * Skv
                                             + jt * KTILE + c0);
                    sv[0] = mv.x ? sv[0] * 0.125f : -1e9f;
                    sv[1] = mv.y ? sv[1] * 0.125f : -1e9f;
                    sv[2] = mv.z ? sv[2] * 0.125f : -1e9f;
                    sv[3] = mv.w ? sv[3] * 0.125f : -1e9f;
                }
                float tmax = fmaxf(fmaxf(sv[0], sv[1]), fmaxf(sv[2], sv[3]));
#pragma unroll
                for (int off = 1; off < 16; off <<= 1)
                    tmax = fmaxf(tmax, __shfl_xor_sync(0xffffffffu, tmax, off));
                float newm = fmaxf(m_i[i], tmax);
                float p[4], rs = 0.f;
#pragma unroll
                for (int j = 0; j < 4; j++) { p[j] = __expf(sv[j] - newm); rs += p[j]; }
#pragma unroll
                for (int off = 1; off < 16; off <<= 1)
                    rs += __shfl_xor_sync(0xffffffffu, rs, off);
                alpha[i] = __expf(m_i[i] - newm);
                l_i[i] = l_i[i] * alpha[i] + rs;
                m_i[i] = newm;
                *(float4*)&p_s[(r0 + i) * 68 + c0] = make_float4(p[0], p[1], p[2], p[3]);
            }
        }
        __syncthreads();   // p_s visible to all

        // rescale running output by alpha (packed per row-pair)
#pragma unroll
        for (int ip = 0; ip < 4; ip++) {
            unsigned long long am = pk2(alpha[2 * ip], alpha[2 * ip + 1]);
#pragma unroll
            for (int j = 0; j < 4; j++) mul2(o2[ip][j], am);
        }

        // ---- O += P V ----
#pragma unroll 4
        for (int kv = 0; kv < 64; kv++) {
            float4 vv = *(const float4*)&v_s[kv * 68 + c0];
            unsigned long long vd[4] = {pk2(vv.x, vv.x), pk2(vv.y, vv.y),
                                        pk2(vv.z, vv.z), pk2(vv.w, vv.w)};
#pragma unroll
            for (int ip = 0; ip < 4; ip++) {
                unsigned long long pp = pk2(p_s[(r0 + 2 * ip) * 68 + kv],
                                            p_s[(r0 + 2 * ip + 1) * 68 + kv]);
#pragma unroll
                for (int j = 0; j < 4; j++)
                    fma2(o2[ip][j], pp, vd[j]);
            }
        }
    }

    // ---- final normalize + store ----
#pragma unroll
    for (int ip = 0; ip < 4; ip++) {
        float lo[4], hi[4];
#pragma unroll
        for (int j = 0; j < 4; j++) upk2(o2[ip][j], lo[j], hi[j]);
        float invl = 1.f / l_i[2 * ip];
        float invh = 1.f / l_i[2 * ip + 1];
        float* p0 = O + qbase + (size_t)(r0 + 2 * ip) * D_MODEL + c0;
        float* p1 = O + qbase + (size_t)(r0 + 2 * ip + 1) * D_MODEL + c0;
        *(float4*)p0 = make_float4(lo[0] * invl, lo[1] * invl, lo[2] * invl, lo[3] * invl);
        *(float4*)p1 = make_float4(hi[0] * invh, hi[1] * invh, hi[2] * invh, hi[3] * invh);
    }
}

// ---------------- fused residual add + LayerNorm ----------------------------
__global__ void __launch_bounds__(256) add_ln_kernel(
    const float* __restrict__ a, const float* __restrict__ r,
    const float* __restrict__ g, const float* __restrict__ be,
    float* __restrict__ out)
{
    const int row = blockIdx.x;
    const int t = threadIdx.x;
    const size_t base = (size_t)row * D_MODEL;

    float4 va = *(const float4*)(a + base + t * 4);
    float4 vr = *(const float4*)(r + base + t * 4);
    float v[4] = {va.x + vr.x, va.y + vr.y, va.z + vr.z, va.w + vr.w};

    float s = v[0] + v[1] + v[2] + v[3];
    float q = v[0]*v[0] + v[1]*v[1] + v[2]*v[2] + v[3]*v[3];
#pragma unroll
    for (int off = 16; off >= 1; off >>= 1) {
        s += __shfl_down_sync(0xffffffffu, s, off);
        q += __shfl_down_sync(0xffffffffu, q, off);
    }
    __shared__ float shs[8], shq[8], fin[2];
    int w = t >> 5, lane = t & 31;
    if (lane == 0) { shs[w] = s; shq[w] = q; }
    __syncthreads();
    if (t == 0) {
        float as = 0.f, aq = 0.f;
#pragma unroll
        for (int i = 0; i < 8; i++) { as += shs[i]; aq += shq[i]; }
        fin[0] = as; fin[1] = aq;
    }
    __syncthreads();
    float mu  = fin[0] * (1.f / D_MODEL);
    float var = fin[1] * (1.f / D_MODEL) - mu * mu;
    float rstd = rsqrtf(var + 1e-5f);

    float4 vg = *(const float4*)(g + t * 4);
    float4 vb = *(const float4*)(be + t * 4);
    float4 o;
    o.x = (v[0] - mu) * rstd * vg.x + vb.x;
    o.y = (v[1] - mu) * rstd * vg.y + vb.y;
    o.z = (v[2] - mu) * rstd * vg.z + vb.z;
    o.w = (v[3] - mu) * rstd * vg.w + vb.w;
    *(float4*)(out + base + t * 4) = o;
}

// ---------------- launch ----------------------------------------------------
static void run_gemm(const float* A, const float* W, const float* b, float* C,
                     int M, int N, int K, bool relu)
{
    dim3 grid(N / 128, M / 128);
    if (relu) sgemm_bias<true><<<grid, 256>>>(A, W, b, C, M, N, K);
    else      sgemm_bias<false><<<grid, 256>>>(A, W, b, C, M, N, K);
}

extern "C" void kernel_launch(void* const* d_in, const int* in_sizes, int n_in,
                              void* d_out, int out_size)
{
    (void)in_sizes; (void)n_in; (void)out_size;
    const float* x    = (const float*)d_in[0];
    const float* enc  = (const float*)d_in[1];
    const int* src_mask = (const int*)d_in[2];
    const int* tgt_mask = (const int*)d_in[3];
    const float* sa_Wq = (const float*)d_in[4];
    const float* sa_bq = (const float*)d_in[5];
    const float* sa_Wk = (const float*)d_in[6];
    const float* sa_bk = (const float*)d_in[7];
    const float* sa_Wv = (const float*)d_in[8];
    const float* sa_bv = (const float*)d_in[9];
    const float* sa_Wo = (const float*)d_in[10];
    const float* sa_bo = (const float*)d_in[11];
    const float* ca_Wq = (const float*)d_in[12];
    const float* ca_bq = (const float*)d_in[13];
    const float* ca_Wk = (const float*)d_in[14];
    const float* ca_bk = (const float*)d_in[15];
    const float* ca_Wv = (const float*)d_in[16];
    const float* ca_bv = (const float*)d_in[17];
    const float* ca_Wo = (const float*)d_in[18];
    const float* ca_bo = (const float*)d_in[19];
    const float* ff_W1 = (const float*)d_in[20];
    const float* ff_b1 = (const float*)d_in[21];
    const float* ff_W2 = (const float*)d_in[22];
    const float* ff_b2 = (const float*)d_in[23];
    const float* ln1_g = (const float*)d_in[24];
    const float* ln1_b = (const float*)d_in[25];
    const float* ln2_g = (const float*)d_in[26];
    const float* ln2_b = (const float*)d_in[27];
    const float* ln3_g = (const float*)d_in[28];
    const float* ln3_b = (const float*)d_in[29];
    float* out = (float*)d_out;

    float *q, *k, *v, *ctx, *tmp, *x1, *x2, *ff;
    cudaGetSymbolAddress((void**)&q,   g_q);
    cudaGetSymbolAddress((void**)&k,   g_k);
    cudaGetSymbolAddress((void**)&v,   g_v);
    cudaGetSymbolAddress((void**)&ctx, g_ctx);
    cudaGetSymbolAddress((void**)&tmp, g_tmp);
    cudaGetSymbolAddress((void**)&x1,  g_x1);
    cudaGetSymbolAddress((void**)&x2,  g_x2);
    cudaGetSymbolAddress((void**)&ff,  g_ff);

    const int ATTN_SMEM = ATTN_SMEM_FLOATS * (int)sizeof(float);  // 103424
    cudaFuncSetAttribute(attn_kernel, cudaFuncAttributeMaxDynamicSharedMemorySize, ATTN_SMEM);

    dim3 agrid(SEQ / QTILE, NHEAD, BATCH);

    // ---- self-attention ----
    run_gemm(x, sa_Wq, sa_bq, q, MROWS, D_MODEL, D_MODEL, false);
    run_gemm(x, sa_Wk, sa_bk, k, MROWS, D_MODEL, D_MODEL, false);
    run_gemm(x, sa_Wv, sa_bv, v, MROWS, D_MODEL, D_MODEL, false);
    attn_kernel<<<agrid, 256, ATTN_SMEM>>>(q, k, v, tgt_mask, ctx, SEQ, 1);
    run_gemm(ctx, sa_Wo, sa_bo, tmp, MROWS, D_MODEL, D_MODEL, false);
    add_ln_kernel<<<MROWS, 256>>>(x, tmp, ln1_g, ln1_b, x1);

    // ---- cross-attention ----
    run_gemm(x1,  ca_Wq, ca_bq, q, MROWS, D_MODEL, D_MODEL, false);
    run_gemm(enc, ca_Wk, ca_bk, k, MROWS, D_MODEL, D_MODEL, false);
    run_gemm(enc, ca_Wv, ca_bv, v, MROWS, D_MODEL, D_MODEL, false);
    attn_kernel<<<agrid, 256, ATTN_SMEM>>>(q, k, v, src_mask, ctx, SEQ, 0);
    run_gemm(ctx, ca_Wo, ca_bo, tmp, MROWS, D_MODEL, D_MODEL, false);
    add_ln_kernel<<<MROWS, 256>>>(x1, tmp, ln2_g, ln2_b, x2);

    // ---- feed-forward ----
    run_gemm(x2, ff_W1, ff_b1, ff, MROWS, DFF_SZ, D_MODEL, true);
    run_gemm(ff, ff_W2, ff_b2, tmp, MROWS, D_MODEL, DFF_SZ, false);
    add_ln_kernel<<<MROWS, 256>>>(x2, tmp, ln3_g, ln3_b, out);
}

// round 4
// speedup vs baseline: 1.6038x; 1.6038x over previous
#include <cuda_runtime.h>
#include <cstdint>

#define D_MODEL 1024
#define NHEAD   16
#define DHEAD   64
#define DFF_SZ  4096
#define BATCH   2
#define SEQ     2048
#define MROWS   (BATCH*SEQ)   // 4096

// ---------------- scratch (device globals; no allocations allowed) ----------
__device__ float g_q  [(size_t)MROWS * D_MODEL];
__device__ float g_k  [(size_t)MROWS * D_MODEL];
__device__ float g_v  [(size_t)MROWS * D_MODEL];
__device__ float g_ctx[(size_t)MROWS * D_MODEL];
__device__ float g_tmp[(size_t)MROWS * D_MODEL];
__device__ float g_x1 [(size_t)MROWS * D_MODEL];
__device__ float g_x2 [(size_t)MROWS * D_MODEL];
__device__ float g_ff [(size_t)MROWS * DFF_SZ];

// ============================================================================
// TF32 tensor-core GEMM (mma.sync m16n8k8, sm_80-level PTX -> legacy HMMA)
// C[M,N] = A[M,K] @ W[N,K]^T + bias, optional ReLU.
// 128x128 CTA tile, BK=32, 8 warps (2x4), warp tile 64x32 (4x4 of m16n8k8).
// ============================================================================
#define ASTRIDE 36                       // pad: bank=(4r+c)%32 -> conflict-free
#define STAGE_F (128 * ASTRIDE)          // floats per stage per matrix
#define GEMM_SMEM (4 * STAGE_F * 4)      // A0,A1,B0,B1 = 73728 bytes

__device__ __forceinline__ float to_tf32(float x) {
    uint32_t u;
    asm("cvt.rna.tf32.f32 %0, %1;" : "=r"(u) : "f"(x));
    return __uint_as_float(u);
}

__device__ __forceinline__ void mma_tf32(float d[4], const uint32_t a[4],
                                         const uint32_t b[2]) {
    asm volatile(
        "mma.sync.aligned.m16n8k8.row.col.f32.tf32.tf32.f32 "
        "{%0,%1,%2,%3}, {%4,%5,%6,%7}, {%8,%9}, {%0,%1,%2,%3};"
        : "+f"(d[0]), "+f"(d[1]), "+f"(d[2]), "+f"(d[3])
        : "r"(a[0]), "r"(a[1]), "r"(a[2]), "r"(a[3]), "r"(b[0]), "r"(b[1]));
}

__global__ void __launch_bounds__(256, 1) gemm_tc(
    const float* __restrict__ A, const float* __restrict__ W,
    const float* __restrict__ bias, float* __restrict__ C,
    int M, int N, int K, int relu)
{
    extern __shared__ float smem[];
    float* sA = smem;                    // [2][128][ASTRIDE]
    float* sB = smem + 2 * STAGE_F;      // [2][128][ASTRIDE]

    const int t      = threadIdx.x;
    const int lane   = t & 31;
    const int wid    = t >> 5;
    const int warp_m = wid >> 2;         // 0..1
    const int warp_n = wid & 3;          // 0..3
    const int lr     = lane >> 2;        // 0..7
    const int lc     = lane & 3;         // 0..3
    const int bm     = blockIdx.y;
    const int bn     = blockIdx.x;

    // gmem load geometry: each thread 4 float4 from A and 4 from W per chunk
    const int row  = t >> 1;             // 0..127
    const int half = t & 1;              // 0,1 -> cols half*16..+15
    const float* gA = A + (size_t)(bm * 128 + row) * K + half * 16;
    const float* gW = W + (size_t)(bn * 128 + row) * K + half * 16;
    float* stA = sA + row * ASTRIDE + half * 16;
    float* stB = sB + row * ASTRIDE + half * 16;

    float acc[4][4][4];
#pragma unroll
    for (int m = 0; m < 4; m++)
#pragma unroll
        for (int n = 0; n < 4; n++)
#pragma unroll
            for (int e = 0; e < 4; e++) acc[m][n][e] = 0.f;

    const int nchunk = K >> 5;
    float4 ra[4], rb[4];

    // prologue: chunk 0 -> regs -> (cvt) -> stage 0
#pragma unroll
    for (int i = 0; i < 4; i++) {
        ra[i] = *(const float4*)(gA + i * 4);
        rb[i] = *(const float4*)(gW + i * 4);
    }
#pragma unroll
    for (int i = 0; i < 4; i++) {
        *(float4*)(stA + i * 4) = make_float4(to_tf32(ra[i].x), to_tf32(ra[i].y),
                                              to_tf32(ra[i].z), to_tf32(ra[i].w));
        *(float4*)(stB + i * 4) = make_float4(to_tf32(rb[i].x), to_tf32(rb[i].y),
                                              to_tf32(rb[i].z), to_tf32(rb[i].w));
    }
    __syncthreads();

    for (int c = 0; c < nchunk; c++) {
        const int stage = c & 1;
        if (c + 1 < nchunk) {
            const float* ga = gA + (c + 1) * 32;
            const float* gw = gW + (c + 1) * 32;
#pragma unroll
            for (int i = 0; i < 4; i++) {
                ra[i] = *(const float4*)(ga + i * 4);
                rb[i] = *(const float4*)(gw + i * 4);
            }
        }

        // ---- MMA over current stage ----
        const float* wa = sA + stage * STAGE_F + (warp_m * 64 + lr) * ASTRIDE + lc;
        const float* wb = sB + stage * STAGE_F + (warp_n * 32 + lr) * ASTRIDE + lc;
#pragma unroll
        for (int s = 0; s < 4; s++) {
            uint32_t af[4][4], bf[4][2];
#pragma unroll
            for (int m = 0; m < 4; m++) {
                const float* p = wa + m * 16 * ASTRIDE + s * 8;
                af[m][0] = __float_as_uint(p[0]);
                af[m][1] = __float_as_uint(p[8 * ASTRIDE]);
                af[m][2] = __float_as_uint(p[4]);
                af[m][3] = __float_as_uint(p[8 * ASTRIDE + 4]);
            }
#pragma unroll
            for (int n = 0; n < 4; n++) {
                const float* p = wb + n * 8 * ASTRIDE + s * 8;
                bf[n][0] = __float_as_uint(p[0]);
                bf[n][1] = __float_as_uint(p[4]);
            }
#pragma unroll
            for (int m = 0; m < 4; m++)
#pragma unroll
                for (int n = 0; n < 4; n++)
                    mma_tf32(acc[m][n], af[m], bf[n]);
        }

        if (c + 1 < nchunk) {
            __syncthreads();
            const int ns = 1 - stage;
            float* da = stA + ns * STAGE_F;
            float* db = stB + ns * STAGE_F;
#pragma unroll
            for (int i = 0; i < 4; i++) {
                *(float4*)(da + i * 4) = make_float4(to_tf32(ra[i].x), to_tf32(ra[i].y),
                                                     to_tf32(ra[i].z), to_tf32(ra[i].w));
                *(float4*)(db + i * 4) = make_float4(to_tf32(rb[i].x), to_tf32(rb[i].y),
                                                     to_tf32(rb[i].z), to_tf32(rb[i].w));
            }
            __syncthreads();
        }
    }

    // ---- epilogue: fragment-layout float2 stores with fused bias/ReLU ----
    const int r0  = bm * 128 + warp_m * 64;
    const int c0g = bn * 128 + warp_n * 32;
#pragma unroll
    for (int n = 0; n < 4; n++) {
        const int col = c0g + n * 8 + 2 * lc;
        float2 bv = *(const float2*)(bias + col);
#pragma unroll
        for (int m = 0; m < 4; m++) {
            const int r = r0 + m * 16 + lr;
            float2 v0 = make_float2(acc[m][n][0] + bv.x, acc[m][n][1] + bv.y);
            float2 v1 = make_float2(acc[m][n][2] + bv.x, acc[m][n][3] + bv.y);
            if (relu) {
                v0.x = fmaxf(v0.x, 0.f); v0.y = fmaxf(v0.y, 0.f);
                v1.x = fmaxf(v1.x, 0.f); v1.y = fmaxf(v1.y, 0.f);
            }
            *(float2*)(C + (size_t)r * N + col)       = v0;
            *(float2*)(C + (size_t)(r + 8) * N + col) = v1;
        }
    }
}

// ============================================================================
// Fused attention (flash-style, 64x64 tiles, DK=64) — R1 version (known good)
// ============================================================================
#define PCH 68
__global__ void __launch_bounds__(256, 2) attn_kernel(
    const float* __restrict__ Q, const float* __restrict__ K,
    const float* __restrict__ V, const int* __restrict__ mask,
    float* __restrict__ O, int Skv, int causal)
{
    extern __shared__ float sm[];
    float* q_s = sm;
    float* k_s = sm + 64 * PCH;
    float* v_s = sm + 2 * 64 * PCH;
    float* p_s = sm + 3 * 64 * PCH;

    const int t  = threadIdx.x;
    const int ty = t >> 4;
    const int tx = t & 15;
    const int qt = blockIdx.x;
    const int h  = blockIdx.y;
    const int b  = blockIdx.z;

    const size_t qbase = ((size_t)(b * SEQ + qt * 64)) * D_MODEL + h * DHEAD;

#pragma unroll
    for (int e = 0; e < 16; e++) {
        int lin = e * 256 + t;
        int r = lin >> 6, d = lin & 63;
        q_s[d * PCH + r] = Q[qbase + (size_t)r * D_MODEL + d];
    }

    float m_i[4], l_i[4], o_acc[4][4];
#pragma unroll
    for (int i = 0; i < 4; i++) {
        m_i[i] = -1e30f;
        l_i[i] = 0.f;
#pragma unroll
        for (int j = 0; j < 4; j++) o_acc[i][j] = 0.f;
    }

    const int ntiles = causal ? (qt + 1) : (Skv >> 6);

    for (int jt = 0; jt < ntiles; jt++) {
        __syncthreads();
        const size_t kbase = ((size_t)(b * Skv + jt * 64)) * D_MODEL + h * DHEAD;
#pragma unroll
        for (int e = 0; e < 16; e++) {
            int lin = e * 256 + t;
            int r = lin >> 6, d = lin & 63;
            float kvv = K[kbase + (size_t)r * D_MODEL + d];
            float vvv = V[kbase + (size_t)r * D_MODEL + d];
            k_s[d * PCH + r] = kvv;
            v_s[r * PCH + d] = vvv;
        }
        __syncthreads();

        float s_acc[4][4];
#pragma unroll
        for (int i = 0; i < 4; i++)
#pragma unroll
            for (int j = 0; j < 4; j++) s_acc[i][j] = 0.f;

#pragma unroll 8
        for (int d = 0; d < 64; d++) {
            float4 qa = *(const float4*)&q_s[d * PCH + ty * 4];
            float4 kb = *(const float4*)&k_s[d * PCH + tx * 4];
            float qv[4] = {qa.x, qa.y, qa.z, qa.w};
            float kv[4] = {kb.x, kb.y, kb.z, kb.w};
#pragma unroll
            for (int i = 0; i < 4; i++)
#pragma unroll
                for (int j = 0; j < 4; j++)
                    s_acc[i][j] = fmaf(qv[i], kv[j], s_acc[i][j]);
        }

#pragma unroll
        for (int i = 0; i < 4; i++) {
            int qg = qt * 64 + ty * 4 + i;
            const int* mp = mask + ((size_t)b * SEQ + qg) * Skv + jt * 64 + tx * 4;
            float tmax = -1e30f;
#pragma unroll
            for (int j = 0; j < 4; j++) {
                float s = s_acc[i][j] * 0.125f;
                if (mp[j] == 0) s = -1e9f;
                s_acc[i][j] = s;
                tmax = fmaxf(tmax, s);
            }
#pragma unroll
            for (int off = 1; off < 16; off <<= 1)
                tmax = fmaxf(tmax, __shfl_xor_sync(0xffffffffu, tmax, off));
            float newm = fmaxf(m_i[i], tmax);
            float rs = 0.f;
            float p[4];
#pragma unroll
            for (int j = 0; j < 4; j++) {
                p[j] = __expf(s_acc[i][j] - newm);
                rs += p[j];
            }
#pragma unroll
            for (int off = 1; off < 16; off <<= 1)
                rs += __shfl_xor_sync(0xffffffffu, rs, off);
            float alpha = __expf(m_i[i] - newm);
            l_i[i] = l_i[i] * alpha + rs;
            m_i[i] = newm;
#pragma unroll
            for (int j = 0; j < 4; j++) {
                o_acc[i][j] *= alpha;
                p_s[(tx * 4 + j) * PCH + ty * 4 + i] = p[j];
            }
        }
        __syncthreads();

#pragma unroll 8
        for (int kv = 0; kv < 64; kv++) {
            float4 pv = *(const float4*)&p_s[kv * PCH + ty * 4];
            float4 vv = *(const float4*)&v_s[kv * PCH + tx * 4];
            float pr[4] = {pv.x, pv.y, pv.z, pv.w};
            float vr[4] = {vv.x, vv.y, vv.z, vv.w};
#pragma unroll
            for (int i = 0; i < 4; i++)
#pragma unroll
                for (int j = 0; j < 4; j++)
                    o_acc[i][j] = fmaf(pr[i], vr[j], o_acc[i][j]);
        }
    }

#pragma unroll
    for (int i = 0; i < 4; i++) {
        float inv = 1.f / l_i[i];
        size_t ob = qbase + (size_t)(ty * 4 + i) * D_MODEL + tx * 4;
        O[ob + 0] = o_acc[i][0] * inv;
        O[ob + 1] = o_acc[i][1] * inv;
        O[ob + 2] = o_acc[i][2] * inv;
        O[ob + 3] = o_acc[i][3] * inv;
    }
}

// ---------------- fused residual add + LayerNorm ----------------------------
__global__ void __launch_bounds__(256) add_ln_kernel(
    const float* __restrict__ a, const float* __restrict__ r,
    const float* __restrict__ g, const float* __restrict__ be,
    float* __restrict__ out)
{
    const int row = blockIdx.x;
    const int t = threadIdx.x;
    const size_t base = (size_t)row * D_MODEL;

    float4 va = *(const float4*)(a + base + t * 4);
    float4 vr = *(const float4*)(r + base + t * 4);
    float v[4] = {va.x + vr.x, va.y + vr.y, va.z + vr.z, va.w + vr.w};

    float s = v[0] + v[1] + v[2] + v[3];
    float q = v[0]*v[0] + v[1]*v[1] + v[2]*v[2] + v[3]*v[3];
#pragma unroll
    for (int off = 16; off >= 1; off >>= 1) {
        s += __shfl_down_sync(0xffffffffu, s, off);
        q += __shfl_down_sync(0xffffffffu, q, off);
    }
    __shared__ float shs[8], shq[8], fin[2];
    int w = t >> 5, lane = t & 31;
    if (lane == 0) { shs[w] = s; shq[w] = q; }
    __syncthreads();
    if (t == 0) {
        float as = 0.f, aq = 0.f;
#pragma unroll
        for (int i = 0; i < 8; i++) { as += shs[i]; aq += shq[i]; }
        fin[0] = as; fin[1] = aq;
    }
    __syncthreads();
    float mu  = fin[0] * (1.f / D_MODEL);
    float var = fin[1] * (1.f / D_MODEL) - mu * mu;
    float rstd = rsqrtf(var + 1e-5f);

    float4 vg = *(const float4*)(g + t * 4);
    float4 vb = *(const float4*)(be + t * 4);
    float4 o;
    o.x = (v[0] - mu) * rstd * vg.x + vb.x;
    o.y = (v[1] - mu) * rstd * vg.y + vb.y;
    o.z = (v[2] - mu) * rstd * vg.z + vb.z;
    o.w = (v[3] - mu) * rstd * vg.w + vb.w;
    *(float4*)(out + base + t * 4) = o;
}

// ---------------- launch ----------------------------------------------------
static void run_gemm(const float* A, const float* W, const float* b, float* C,
                     int M, int N, int K, bool relu)
{
    dim3 grid(N / 128, M / 128);
    gemm_tc<<<grid, 256, GEMM_SMEM>>>(A, W, b, C, M, N, K, relu ? 1 : 0);
}

extern "C" void kernel_launch(void* const* d_in, const int* in_sizes, int n_in,
                              void* d_out, int out_size)
{
    (void)in_sizes; (void)n_in; (void)out_size;
    const float* x    = (const float*)d_in[0];
    const float* enc  = (const float*)d_in[1];
    const int* src_mask = (const int*)d_in[2];
    const int* tgt_mask = (const int*)d_in[3];
    const float* sa_Wq = (const float*)d_in[4];
    const float* sa_bq = (const float*)d_in[5];
    const float* sa_Wk = (const float*)d_in[6];
    const float* sa_bk = (const float*)d_in[7];
    const float* sa_Wv = (const float*)d_in[8];
    const float* sa_bv = (const float*)d_in[9];
    const float* sa_Wo = (const float*)d_in[10];
    const float* sa_bo = (const float*)d_in[11];
    const float* ca_Wq = (const float*)d_in[12];
    const float* ca_bq = (const float*)d_in[13];
    const float* ca_Wk = (const float*)d_in[14];
    const float* ca_bk = (const float*)d_in[15];
    const float* ca_Wv = (const float*)d_in[16];
    const float* ca_bv = (const float*)d_in[17];
    const float* ca_Wo = (const float*)d_in[18];
    const float* ca_bo = (const float*)d_in[19];
    const float* ff_W1 = (const float*)d_in[20];
    const float* ff_b1 = (const float*)d_in[21];
    const float* ff_W2 = (const float*)d_in[22];
    const float* ff_b2 = (const float*)d_in[23];
    const float* ln1_g = (const float*)d_in[24];
    const float* ln1_b = (const float*)d_in[25];
    const float* ln2_g = (const float*)d_in[26];
    const float* ln2_b = (const float*)d_in[27];
    const float* ln3_g = (const float*)d_in[28];
    const float* ln3_b = (const float*)d_in[29];
    float* out = (float*)d_out;

    float *q, *k, *v, *ctx, *tmp, *x1, *x2, *ff;
    cudaGetSymbolAddress((void**)&q,   g_q);
    cudaGetSymbolAddress((void**)&k,   g_k);
    cudaGetSymbolAddress((void**)&v,   g_v);
    cudaGetSymbolAddress((void**)&ctx, g_ctx);
    cudaGetSymbolAddress((void**)&tmp, g_tmp);
    cudaGetSymbolAddress((void**)&x1,  g_x1);
    cudaGetSymbolAddress((void**)&x2,  g_x2);
    cudaGetSymbolAddress((void**)&ff,  g_ff);

    cudaFuncSetAttribute(gemm_tc, cudaFuncAttributeMaxDynamicSharedMemorySize,
                         GEMM_SMEM);
    const int ATTN_SMEM = 4 * 64 * PCH * sizeof(float);
    cudaFuncSetAttribute(attn_kernel, cudaFuncAttributeMaxDynamicSharedMemorySize,
                         ATTN_SMEM);

    dim3 agrid(SEQ / 64, NHEAD, BATCH);

    // ---- self-attention ----
    run_gemm(x, sa_Wq, sa_bq, q, MROWS, D_MODEL, D_MODEL, false);
    run_gemm(x, sa_Wk, sa_bk, k, MROWS, D_MODEL, D_MODEL, false);
    run_gemm(x, sa_Wv, sa_bv, v, MROWS, D_MODEL, D_MODEL, false);
    attn_kernel<<<agrid, 256, ATTN_SMEM>>>(q, k, v, tgt_mask, ctx, SEQ, 1);
    run_gemm(ctx, sa_Wo, sa_bo, tmp, MROWS, D_MODEL, D_MODEL, false);
    add_ln_kernel<<<MROWS, 256>>>(x, tmp, ln1_g, ln1_b, x1);

    // ---- cross-attention ----
    run_gemm(x1,  ca_Wq, ca_bq, q, MROWS, D_MODEL, D_MODEL, false);
    run_gemm(enc, ca_Wk, ca_bk, k, MROWS, D_MODEL, D_MODEL, false);
    run_gemm(enc, ca_Wv, ca_bv, v, MROWS, D_MODEL, D_MODEL, false);
    attn_kernel<<<agrid, 256, ATTN_SMEM>>>(q, k, v, src_mask, ctx, SEQ, 0);
    run_gemm(ctx, ca_Wo, ca_bo, tmp, MROWS, D_MODEL, D_MODEL, false);
    add_ln_kernel<<<MROWS, 256>>>(x1, tmp, ln2_g, ln2_b, x2);

    // ---- feed-forward ----
    run_gemm(x2, ff_W1, ff_b1, ff, MROWS, DFF_SZ, D_MODEL, true);
    run_gemm(ff, ff_W2, ff_b2, tmp, MROWS, D_MODEL, DFF_SZ, false);
    add_ln_kernel<<<MROWS, 256>>>(x2, tmp, ln3_g, ln3_b, out);
}

// round 5
// speedup vs baseline: 2.4636x; 1.5361x over previous
#include <cuda_runtime.h>
#include <cstdint>

#define D_MODEL 1024
#define NHEAD   16
#define DHEAD   64
#define DFF_SZ  4096
#define BATCH   2
#define SEQ     2048
#define MROWS   (BATCH*SEQ)   // 4096

// ---------------- scratch (device globals; no allocations allowed) ----------
__device__ float g_q  [(size_t)MROWS * D_MODEL];
__device__ float g_k  [(size_t)MROWS * D_MODEL];
__device__ float g_v  [(size_t)MROWS * D_MODEL];
__device__ float g_ctx[(size_t)MROWS * D_MODEL];
__device__ float g_tmp[(size_t)MROWS * D_MODEL];
__device__ float g_x1 [(size_t)MROWS * D_MODEL];
__device__ float g_x2 [(size_t)MROWS * D_MODEL];
__device__ float g_ff [(size_t)MROWS * DFF_SZ];

// ---------------- tf32 helpers ----------------------------------------------
__device__ __forceinline__ float to_tf32(float x) {
    uint32_t u;
    asm("cvt.rna.tf32.f32 %0, %1;" : "=r"(u) : "f"(x));
    return __uint_as_float(u);
}

__device__ __forceinline__ void mma_tf32(float d[4], const uint32_t a[4],
                                         const uint32_t b[2]) {
    asm volatile(
        "mma.sync.aligned.m16n8k8.row.col.f32.tf32.tf32.f32 "
        "{%0,%1,%2,%3}, {%4,%5,%6,%7}, {%8,%9}, {%0,%1,%2,%3};"
        : "+f"(d[0]), "+f"(d[1]), "+f"(d[2]), "+f"(d[3])
        : "r"(a[0]), "r"(a[1]), "r"(a[2]), "r"(a[3]), "r"(b[0]), "r"(b[1]));
}

// ============================================================================
// TF32 tensor-core GEMM (R4, unchanged): C = A @ W^T + bias, optional ReLU
// ============================================================================
#define ASTRIDE 36
#define STAGE_F (128 * ASTRIDE)
#define GEMM_SMEM (4 * STAGE_F * 4)

__global__ void __launch_bounds__(256, 1) gemm_tc(
    const float* __restrict__ A, const float* __restrict__ W,
    const float* __restrict__ bias, float* __restrict__ C,
    int M, int N, int K, int relu)
{
    extern __shared__ float smem[];
    float* sA = smem;
    float* sB = smem + 2 * STAGE_F;

    const int t      = threadIdx.x;
    const int lane   = t & 31;
    const int wid    = t >> 5;
    const int warp_m = wid >> 2;
    const int warp_n = wid & 3;
    const int lr     = lane >> 2;
    const int lc     = lane & 3;
    const int bm     = blockIdx.y;
    const int bn     = blockIdx.x;

    const int row  = t >> 1;
    const int half = t & 1;
    const float* gA = A + (size_t)(bm * 128 + row) * K + half * 16;
    const float* gW = W + (size_t)(bn * 128 + row) * K + half * 16;
    float* stA = sA + row * ASTRIDE + half * 16;
    float* stB = sB + row * ASTRIDE + half * 16;

    float acc[4][4][4];
#pragma unroll
    for (int m = 0; m < 4; m++)
#pragma unroll
        for (int n = 0; n < 4; n++)
#pragma unroll
            for (int e = 0; e < 4; e++) acc[m][n][e] = 0.f;

    const int nchunk = K >> 5;
    float4 ra[4], rb[4];

#pragma unroll
    for (int i = 0; i < 4; i++) {
        ra[i] = *(const float4*)(gA + i * 4);
        rb[i] = *(const float4*)(gW + i * 4);
    }
#pragma unroll
    for (int i = 0; i < 4; i++) {
        *(float4*)(stA + i * 4) = make_float4(to_tf32(ra[i].x), to_tf32(ra[i].y),
                                              to_tf32(ra[i].z), to_tf32(ra[i].w));
        *(float4*)(stB + i * 4) = make_float4(to_tf32(rb[i].x), to_tf32(rb[i].y),
                                              to_tf32(rb[i].z), to_tf32(rb[i].w));
    }
    __syncthreads();

    for (int c = 0; c < nchunk; c++) {
        const int stage = c & 1;
        if (c + 1 < nchunk) {
            const float* ga = gA + (c + 1) * 32;
            const float* gw = gW + (c + 1) * 32;
#pragma unroll
            for (int i = 0; i < 4; i++) {
                ra[i] = *(const float4*)(ga + i * 4);
                rb[i] = *(const float4*)(gw + i * 4);
            }
        }

        const float* wa = sA + stage * STAGE_F + (warp_m * 64 + lr) * ASTRIDE + lc;
        const float* wb = sB + stage * STAGE_F + (warp_n * 32 + lr) * ASTRIDE + lc;
#pragma unroll
        for (int s = 0; s < 4; s++) {
            uint32_t af[4][4], bf[4][2];
#pragma unroll
            for (int m = 0; m < 4; m++) {
                const float* p = wa + m * 16 * ASTRIDE + s * 8;
                af[m][0] = __float_as_uint(p[0]);
                af[m][1] = __float_as_uint(p[8 * ASTRIDE]);
                af[m][2] = __float_as_uint(p[4]);
                af[m][3] = __float_as_uint(p[8 * ASTRIDE + 4]);
            }
#pragma unroll
            for (int n = 0; n < 4; n++) {
                const float* p = wb + n * 8 * ASTRIDE + s * 8;
                bf[n][0] = __float_as_uint(p[0]);
                bf[n][1] = __float_as_uint(p[4]);
            }
#pragma unroll
            for (int m = 0; m < 4; m++)
#pragma unroll
                for (int n = 0; n < 4; n++)
                    mma_tf32(acc[m][n], af[m], bf[n]);
        }

        if (c + 1 < nchunk) {
            __syncthreads();
            const int ns = 1 - stage;
            float* da = stA + ns * STAGE_F;
            float* db = stB + ns * STAGE_F;
#pragma unroll
            for (int i = 0; i < 4; i++) {
                *(float4*)(da + i * 4) = make_float4(to_tf32(ra[i].x), to_tf32(ra[i].y),
                                                     to_tf32(ra[i].z), to_tf32(ra[i].w));
                *(float4*)(db + i * 4) = make_float4(to_tf32(rb[i].x), to_tf32(rb[i].y),
                                                     to_tf32(rb[i].z), to_tf32(rb[i].w));
            }
            __syncthreads();
        }
    }

    const int r0  = bm * 128 + warp_m * 64;
    const int c0g = bn * 128 + warp_n * 32;
#pragma unroll
    for (int n = 0; n < 4; n++) {
        const int col = c0g + n * 8 + 2 * lc;
        float2 bv = *(const float2*)(bias + col);
#pragma unroll
        for (int m = 0; m < 4; m++) {
            const int r = r0 + m * 16 + lr;
            float2 v0 = make_float2(acc[m][n][0] + bv.x, acc[m][n][1] + bv.y);
            float2 v1 = make_float2(acc[m][n][2] + bv.x, acc[m][n][3] + bv.y);
            if (relu) {
                v0.x = fmaxf(v0.x, 0.f); v0.y = fmaxf(v0.y, 0.f);
                v1.x = fmaxf(v1.x, 0.f); v1.y = fmaxf(v1.y, 0.f);
            }
            *(float2*)(C + (size_t)r * N + col)       = v0;
            *(float2*)(C + (size_t)(r + 8) * N + col) = v1;
        }
    }
}

// ============================================================================
// Tensor-core flash attention: 128 q-rows x 64 k-cols per block, 8 warps.
// Each warp: 16 q-rows. Q frags in regs; K/V/P staged in smem (tf32).
// ============================================================================
#define KP 68
#define VP 72
#define PP 76
#define ATTN_SMEM ((64*KP + 64*VP + 128*PP) * 4)   // 74752 bytes

__global__ void __launch_bounds__(256, 2) attn_tc(
    const float* __restrict__ Q, const float* __restrict__ K,
    const float* __restrict__ V, const int* __restrict__ mask,
    float* __restrict__ O, int Skv, int causal)
{
    extern __shared__ float sm[];
    float* k_s = sm;                       // [64][KP]
    float* v_s = sm + 64 * KP;             // [64][VP]
    float* p_s = sm + 64 * KP + 64 * VP;   // [128][PP]

    const int t    = threadIdx.x;
    const int lane = t & 31;
    const int wid  = t >> 5;
    const int lr   = lane >> 2;
    const int lc   = lane & 3;
    const int wr0  = wid * 16;
    const int qt   = causal ? (gridDim.x - 1 - blockIdx.x) : blockIdx.x;
    const int h    = blockIdx.y;
    const int b    = blockIdx.z;
    const int qrow0 = qt * 128;

    const size_t qbase = ((size_t)(b * SEQ + qrow0)) * D_MODEL + h * DHEAD;

    // ---- stage Q (scaled by 1/8, tf32) into p_s, then frag-load to regs ----
#pragma unroll
    for (int e = 0; e < 8; e++) {
        int f4 = e * 256 + t;          // 0..2047
        int r = f4 >> 4, c4 = f4 & 15;
        float4 qv = *(const float4*)(Q + qbase + (size_t)r * D_MODEL + c4 * 4);
        float* dst = p_s + r * PP + c4 * 4;
        dst[0] = to_tf32(qv.x * 0.125f);
        dst[1] = to_tf32(qv.y * 0.125f);
        dst[2] = to_tf32(qv.z * 0.125f);
        dst[3] = to_tf32(qv.w * 0.125f);
    }
    __syncthreads();
    uint32_t qa[8][4];
#pragma unroll
    for (int kf = 0; kf < 8; kf++) {
        const float* qp = p_s + (wr0 + lr) * PP + kf * 8 + lc;
        qa[kf][0] = __float_as_uint(qp[0]);
        qa[kf][1] = __float_as_uint(qp[8 * PP]);
        qa[kf][2] = __float_as_uint(qp[4]);
        qa[kf][3] = __float_as_uint(qp[8 * PP + 4]);
    }

    float m_i[2] = {-1e30f, -1e30f};
    float l_i[2] = {0.f, 0.f};
    float oacc[8][4];
#pragma unroll
    for (int nf = 0; nf < 8; nf++)
#pragma unroll
        for (int e = 0; e < 4; e++) oacc[nf][e] = 0.f;

    const int r0g = qrow0 + wr0 + lr;
    const int ntiles = causal ? (2 * qt + 2) : (Skv >> 6);

    for (int jt = 0; jt < ntiles; jt++) {
        __syncthreads();   // protect k_s/v_s (and p_s vs Q staging on iter 0)
        const size_t kbase = ((size_t)(b * Skv + jt * 64)) * D_MODEL + h * DHEAD;
#pragma unroll
        for (int e = 0; e < 4; e++) {
            int f4 = e * 256 + t;      // 0..1023
            int r = f4 >> 4, c4 = f4 & 15;
            float4 kv4 = *(const float4*)(K + kbase + (size_t)r * D_MODEL + c4 * 4);
            float4 vv4 = *(const float4*)(V + kbase + (size_t)r * D_MODEL + c4 * 4);
            float* kd = k_s + r * KP + c4 * 4;
            kd[0] = to_tf32(kv4.x); kd[1] = to_tf32(kv4.y);
            kd[2] = to_tf32(kv4.z); kd[3] = to_tf32(kv4.w);
            float* vd = v_s + r * VP + c4 * 4;
            vd[0] = to_tf32(vv4.x); vd[1] = to_tf32(vv4.y);
            vd[2] = to_tf32(vv4.z); vd[3] = to_tf32(vv4.w);
        }
        __syncthreads();

        // ---- S = Q K^T ----
        float sacc[8][4];
#pragma unroll
        for (int nf = 0; nf < 8; nf++)
#pragma unroll
            for (int e = 0; e < 4; e++) sacc[nf][e] = 0.f;

#pragma unroll
        for (int ks = 0; ks < 8; ks++) {
#pragma unroll
            for (int nf = 0; nf < 8; nf++) {
                const float* kp = k_s + (nf * 8 + lr) * KP + ks * 8 + lc;
                uint32_t bf[2] = {__float_as_uint(kp[0]), __float_as_uint(kp[4])};
                mma_tf32(sacc[nf], qa[ks], bf);
            }
        }

        // ---- mask ----
        if (causal) {
            if (jt >= 2 * qt) {
#pragma unroll
                for (int nf = 0; nf < 8; nf++) {
                    int c0 = jt * 64 + nf * 8 + 2 * lc;
                    if (c0     > r0g)     sacc[nf][0] = -1e9f;
                    if (c0 + 1 > r0g)     sacc[nf][1] = -1e9f;
                    if (c0     > r0g + 8) sacc[nf][2] = -1e9f;
                    if (c0 + 1 > r0g + 8) sacc[nf][3] = -1e9f;
                }
            }
        } else {
            const int* mrow0 = mask + ((size_t)b * SEQ + r0g) * Skv + jt * 64;
            const int* mrow1 = mrow0 + 8 * Skv;
#pragma unroll
            for (int nf = 0; nf < 8; nf++) {
                int2 m0 = *(const int2*)(mrow0 + nf * 8 + 2 * lc);
                int2 m1 = *(const int2*)(mrow1 + nf * 8 + 2 * lc);
                if (!m0.x) sacc[nf][0] = -1e9f;
                if (!m0.y) sacc[nf][1] = -1e9f;
                if (!m1.x) sacc[nf][2] = -1e9f;
                if (!m1.y) sacc[nf][3] = -1e9f;
            }
        }

        // ---- online softmax on fragment layout ----
        float mx0 = -1e30f, mx1 = -1e30f;
#pragma unroll
        for (int nf = 0; nf < 8; nf++) {
            mx0 = fmaxf(mx0, fmaxf(sacc[nf][0], sacc[nf][1]));
            mx1 = fmaxf(mx1, fmaxf(sacc[nf][2], sacc[nf][3]));
        }
        mx0 = fmaxf(mx0, __shfl_xor_sync(0xffffffffu, mx0, 1));
        mx0 = fmaxf(mx0, __shfl_xor_sync(0xffffffffu, mx0, 2));
        mx1 = fmaxf(mx1, __shfl_xor_sync(0xffffffffu, mx1, 1));
        mx1 = fmaxf(mx1, __shfl_xor_sync(0xffffffffu, mx1, 2));
        float newm0 = fmaxf(m_i[0], mx0);
        float newm1 = fmaxf(m_i[1], mx1);
        float a0 = __expf(m_i[0] - newm0);
        float a1 = __expf(m_i[1] - newm1);
        m_i[0] = newm0; m_i[1] = newm1;

        float rs0 = 0.f, rs1 = 0.f;
#pragma unroll
        for (int nf = 0; nf < 8; nf++) {
            float p0 = __expf(sacc[nf][0] - newm0);
            float p1 = __expf(sacc[nf][1] - newm0);
            float p2 = __expf(sacc[nf][2] - newm1);
            float p3 = __expf(sacc[nf][3] - newm1);
            rs0 += p0 + p1;
            rs1 += p2 + p3;
            float* pr0 = p_s + (wr0 + lr) * PP + nf * 8 + 2 * lc;
            pr0[0] = to_tf32(p0); pr0[1] = to_tf32(p1);
            float* pr1 = pr0 + 8 * PP;
            pr1[0] = to_tf32(p2); pr1[1] = to_tf32(p3);
            oacc[nf][0] *= a0; oacc[nf][1] *= a0;
            oacc[nf][2] *= a1; oacc[nf][3] *= a1;
        }
        rs0 += __shfl_xor_sync(0xffffffffu, rs0, 1);
        rs0 += __shfl_xor_sync(0xffffffffu, rs0, 2);
        rs1 += __shfl_xor_sync(0xffffffffu, rs1, 1);
        rs1 += __shfl_xor_sync(0xffffffffu, rs1, 2);
        l_i[0] = l_i[0] * a0 + rs0;
        l_i[1] = l_i[1] * a1 + rs1;
        __syncwarp();

        // ---- O += P V ----
#pragma unroll
        for (int ks = 0; ks < 8; ks++) {
            const float* pp = p_s + (wr0 + lr) * PP + ks * 8 + lc;
            uint32_t af[4] = {__float_as_uint(pp[0]),
                              __float_as_uint(pp[8 * PP]),
                              __float_as_uint(pp[4]),
                              __float_as_uint(pp[8 * PP + 4])};
#pragma unroll
            for (int nf = 0; nf < 8; nf++) {
                const float* vp = v_s + (ks * 8 + lc) * VP + nf * 8 + lr;
                uint32_t bf[2] = {__float_as_uint(vp[0]),
                                  __float_as_uint(vp[4 * VP])};
                mma_tf32(oacc[nf], af, bf);
            }
        }
    }

    // ---- normalize + store ----
    float inv0 = 1.f / l_i[0];
    float inv1 = 1.f / l_i[1];
#pragma unroll
    for (int nf = 0; nf < 8; nf++) {
        float* o0 = O + qbase + (size_t)(wr0 + lr) * D_MODEL + nf * 8 + 2 * lc;
        float* o1 = o0 + 8 * D_MODEL;
        *(float2*)o0 = make_float2(oacc[nf][0] * inv0, oacc[nf][1] * inv0);
        *(float2*)o1 = make_float2(oacc[nf][2] * inv1, oacc[nf][3] * inv1);
    }
}

// ---------------- fused residual add + LayerNorm ----------------------------
__global__ void __launch_bounds__(256) add_ln_kernel(
    const float* __restrict__ a, const float* __restrict__ r,
    const float* __restrict__ g, const float* __restrict__ be,
    float* __restrict__ out)
{
    const int row = blockIdx.x;
    const int t = threadIdx.x;
    const size_t base = (size_t)row * D_MODEL;

    float4 va = *(const float4*)(a + base + t * 4);
    float4 vr = *(const float4*)(r + base + t * 4);
    float v[4] = {va.x + vr.x, va.y + vr.y, va.z + vr.z, va.w + vr.w};

    float s = v[0] + v[1] + v[2] + v[3];
    float q = v[0]*v[0] + v[1]*v[1] + v[2]*v[2] + v[3]*v[3];
#pragma unroll
    for (int off = 16; off >= 1; off >>= 1) {
        s += __shfl_down_sync(0xffffffffu, s, off);
        q += __shfl_down_sync(0xffffffffu, q, off);
    }
    __shared__ float shs[8], shq[8], fin[2];
    int w = t >> 5, lane = t & 31;
    if (lane == 0) { shs[w] = s; shq[w] = q; }
    __syncthreads();
    if (t == 0) {
        float as = 0.f, aq = 0.f;
#pragma unroll
        for (int i = 0; i < 8; i++) { as += shs[i]; aq += shq[i]; }
        fin[0] = as; fin[1] = aq;
    }
    __syncthreads();
    float mu  = fin[0] * (1.f / D_MODEL);
    float var = fin[1] * (1.f / D_MODEL) - mu * mu;
    float rstd = rsqrtf(var + 1e-5f);

    float4 vg = *(const float4*)(g + t * 4);
    float4 vb = *(const float4*)(be + t * 4);
    float4 o;
    o.x = (v[0] - mu) * rstd * vg.x + vb.x;
    o.y = (v[1] - mu) * rstd * vg.y + vb.y;
    o.z = (v[2] - mu) * rstd * vg.z + vb.z;
    o.w = (v[3] - mu) * rstd * vg.w + vb.w;
    *(float4*)(out + base + t * 4) = o;
}

// ---------------- launch ----------------------------------------------------
static void run_gemm(const float* A, const float* W, const float* b, float* C,
                     int M, int N, int K, bool relu)
{
    dim3 grid(N / 128, M / 128);
    gemm_tc<<<grid, 256, GEMM_SMEM>>>(A, W, b, C, M, N, K, relu ? 1 : 0);
}

extern "C" void kernel_launch(void* const* d_in, const int* in_sizes, int n_in,
                              void* d_out, int out_size)
{
    (void)in_sizes; (void)n_in; (void)out_size;
    const float* x    = (const float*)d_in[0];
    const float* enc  = (const float*)d_in[1];
    const int* src_mask = (const int*)d_in[2];
    const int* tgt_mask = (const int*)d_in[3];
    const float* sa_Wq = (const float*)d_in[4];
    const float* sa_bq = (const float*)d_in[5];
    const float* sa_Wk = (const float*)d_in[6];
    const float* sa_bk = (const float*)d_in[7];
    const float* sa_Wv = (const float*)d_in[8];
    const float* sa_bv = (const float*)d_in[9];
    const float* sa_Wo = (const float*)d_in[10];
    const float* sa_bo = (const float*)d_in[11];
    const float* ca_Wq = (const float*)d_in[12];
    const float* ca_bq = (const float*)d_in[13];
    const float* ca_Wk = (const float*)d_in[14];
    const float* ca_bk = (const float*)d_in[15];
    const float* ca_Wv = (const float*)d_in[16];
    const float* ca_bv = (const float*)d_in[17];
    const float* ca_Wo = (const float*)d_in[18];
    const float* ca_bo = (const float*)d_in[19];
    const float* ff_W1 = (const float*)d_in[20];
    const float* ff_b1 = (const float*)d_in[21];
    const float* ff_W2 = (const float*)d_in[22];
    const float* ff_b2 = (const float*)d_in[23];
    const float* ln1_g = (const float*)d_in[24];
    const float* ln1_b = (const float*)d_in[25];
    const float* ln2_g = (const float*)d_in[26];
    const float* ln2_b = (const float*)d_in[27];
    const float* ln3_g = (const float*)d_in[28];
    const float* ln3_b = (const float*)d_in[29];
    float* out = (float*)d_out;

    float *q, *k, *v, *ctx, *tmp, *x1, *x2, *ff;
    cudaGetSymbolAddress((void**)&q,   g_q);
    cudaGetSymbolAddress((void**)&k,   g_k);
    cudaGetSymbolAddress((void**)&v,   g_v);
    cudaGetSymbolAddress((void**)&ctx, g_ctx);
    cudaGetSymbolAddress((void**)&tmp, g_tmp);
    cudaGetSymbolAddress((void**)&x1,  g_x1);
    cudaGetSymbolAddress((void**)&x2,  g_x2);
    cudaGetSymbolAddress((void**)&ff,  g_ff);

    cudaFuncSetAttribute(gemm_tc, cudaFuncAttributeMaxDynamicSharedMemorySize,
                         GEMM_SMEM);
    cudaFuncSetAttribute(attn_tc, cudaFuncAttributeMaxDynamicSharedMemorySize,
                         ATTN_SMEM);

    dim3 agrid(SEQ / 128, NHEAD, BATCH);

    // ---- self-attention ----
    run_gemm(x, sa_Wq, sa_bq, q, MROWS, D_MODEL, D_MODEL, false);
    run_gemm(x, sa_Wk, sa_bk, k, MROWS, D_MODEL, D_MODEL, false);
    run_gemm(x, sa_Wv, sa_bv, v, MROWS, D_MODEL, D_MODEL, false);
    attn_tc<<<agrid, 256, ATTN_SMEM>>>(q, k, v, tgt_mask, ctx, SEQ, 1);
    run_gemm(ctx, sa_Wo, sa_bo, tmp, MROWS, D_MODEL, D_MODEL, false);
    add_ln_kernel<<<MROWS, 256>>>(x, tmp, ln1_g, ln1_b, x1);

    // ---- cross-attention ----
    run_gemm(x1,  ca_Wq, ca_bq, q, MROWS, D_MODEL, D_MODEL, false);
    run_gemm(enc, ca_Wk, ca_bk, k, MROWS, D_MODEL, D_MODEL, false);
    run_gemm(enc, ca_Wv, ca_bv, v, MROWS, D_MODEL, D_MODEL, false);
    attn_tc<<<agrid, 256, ATTN_SMEM>>>(q, k, v, src_mask, ctx, SEQ, 0);
    run_gemm(ctx, ca_Wo, ca_bo, tmp, MROWS, D_MODEL, D_MODEL, false);
    add_ln_kernel<<<MROWS, 256>>>(x1, tmp, ln2_g, ln2_b, x2);

    // ---- feed-forward ----
    run_gemm(x2, ff_W1, ff_b1, ff, MROWS, DFF_SZ, D_MODEL, true);
    run_gemm(ff, ff_W2, ff_b2, tmp, MROWS, D_MODEL, DFF_SZ, false);
    add_ln_kernel<<<MROWS, 256>>>(x2, tmp, ln3_g, ln3_b, out);
}

// round 6
// speedup vs baseline: 2.9902x; 1.2138x over previous
#include <cuda_runtime.h>
#include <cstdint>

#define D_MODEL 1024
#define NHEAD   16
#define DHEAD   64
#define DFF_SZ  4096
#define BATCH   2
#define SEQ     2048
#define MROWS   (BATCH*SEQ)   // 4096

// ---------------- scratch (device globals; no allocations allowed) ----------
__device__ float g_q  [(size_t)MROWS * D_MODEL];
__device__ float g_k  [(size_t)MROWS * D_MODEL];
__device__ float g_v  [(size_t)MROWS * D_MODEL];
__device__ float g_ctx[(size_t)MROWS * D_MODEL];
__device__ float g_tmp[(size_t)MROWS * D_MODEL];
__device__ float g_x1 [(size_t)MROWS * D_MODEL];
__device__ float g_x2 [(size_t)MROWS * D_MODEL];
__device__ float g_ff [(size_t)MROWS * DFF_SZ];

// ---------------- tf32 / mma helpers ----------------------------------------
__device__ __forceinline__ float to_tf32(float x) {
    uint32_t u;
    asm("cvt.rna.tf32.f32 %0, %1;" : "=r"(u) : "f"(x));
    return __uint_as_float(u);
}

__device__ __forceinline__ void mma_tf32(float d[4], const uint32_t a[4],
                                         const uint32_t b[2]) {
    asm volatile(
        "mma.sync.aligned.m16n8k8.row.col.f32.tf32.tf32.f32 "
        "{%0,%1,%2,%3}, {%4,%5,%6,%7}, {%8,%9}, {%0,%1,%2,%3};"
        : "+f"(d[0]), "+f"(d[1]), "+f"(d[2]), "+f"(d[3])
        : "r"(a[0]), "r"(a[1]), "r"(a[2]), "r"(a[3]), "r"(b[0]), "r"(b[1]));
}

__device__ __forceinline__ void ldsm_x4(uint32_t r[4], uint32_t addr) {
    asm volatile("ldmatrix.sync.aligned.m8n8.x4.shared.b16 {%0,%1,%2,%3}, [%4];"
                 : "=r"(r[0]), "=r"(r[1]), "=r"(r[2]), "=r"(r[3]) : "r"(addr));
}

// ============================================================================
// TF32 tensor-core GEMM: C = A @ W^T + bias, optional ReLU
// 128x128 CTA tile, BK=32, 8 warps (2x4), warp 64x32, ldmatrix frag loads.
// ============================================================================
#define ASTRIDE 36
#define STAGE_F (128 * ASTRIDE)
#define GEMM_SMEM (4 * STAGE_F * 4)

__global__ void __launch_bounds__(256, 2) gemm_tc(
    const float* __restrict__ A, const float* __restrict__ W,
    const float* __restrict__ bias, float* __restrict__ C,
    int M, int N, int K, int relu)
{
    extern __shared__ float smem[];
    float* sA = smem;
    float* sB = smem + 2 * STAGE_F;

    const int t      = threadIdx.x;
    const int lane   = t & 31;
    const int wid    = t >> 5;
    const int warp_m = wid >> 2;
    const int warp_n = wid & 3;
    const int lr     = lane >> 2;
    const int lc     = lane & 3;
    const int bm     = blockIdx.y;
    const int bn     = blockIdx.x;

    const int row  = t >> 1;
    const int half = t & 1;
    const float* gA = A + (size_t)(bm * 128 + row) * K + half * 16;
    const float* gW = W + (size_t)(bn * 128 + row) * K + half * 16;
    float* stA = sA + row * ASTRIDE + half * 16;
    float* stB = sB + row * ASTRIDE + half * 16;

    // ldmatrix per-thread source offsets (bytes within a stage)
    const int g8 = lane >> 3, r8 = lane & 7;
    uint32_t aoff[4], boff[2];
#pragma unroll
    for (int mt = 0; mt < 4; mt++) {
        int rr = warp_m * 64 + mt * 16 + (g8 & 1) * 8 + r8;
        int cc = (g8 >> 1) * 4;
        aoff[mt] = (rr * ASTRIDE + cc) * 4;
    }
#pragma unroll
    for (int p = 0; p < 2; p++) {
        int rr = warp_n * 32 + p * 16 + (g8 >> 1) * 8 + r8;
        int cc = (g8 & 1) * 4;
        boff[p] = (rr * ASTRIDE + cc) * 4;
    }
    const uint32_t sA_addr = (uint32_t)__cvta_generic_to_shared(sA);
    const uint32_t sB_addr = (uint32_t)__cvta_generic_to_shared(sB);

    float acc[4][4][4];
#pragma unroll
    for (int m = 0; m < 4; m++)
#pragma unroll
        for (int n = 0; n < 4; n++)
#pragma unroll
            for (int e = 0; e < 4; e++) acc[m][n][e] = 0.f;

    const int nchunk = K >> 5;
    float4 ra[4], rb[4];

#pragma unroll
    for (int i = 0; i < 4; i++) {
        ra[i] = *(const float4*)(gA + i * 4);
        rb[i] = *(const float4*)(gW + i * 4);
    }
#pragma unroll
    for (int i = 0; i < 4; i++) {
        *(float4*)(stA + i * 4) = make_float4(to_tf32(ra[i].x), to_tf32(ra[i].y),
                                              to_tf32(ra[i].z), to_tf32(ra[i].w));
        *(float4*)(stB + i * 4) = make_float4(to_tf32(rb[i].x), to_tf32(rb[i].y),
                                              to_tf32(rb[i].z), to_tf32(rb[i].w));
    }
    __syncthreads();

    for (int c = 0; c < nchunk; c++) {
        const int stage = c & 1;
        if (c + 1 < nchunk) {
            const float* ga = gA + (c + 1) * 32;
            const float* gw = gW + (c + 1) * 32;
#pragma unroll
            for (int i = 0; i < 4; i++) {
                ra[i] = *(const float4*)(ga + i * 4);
                rb[i] = *(const float4*)(gw + i * 4);
            }
        }

        const uint32_t abase = sA_addr + stage * (STAGE_F * 4);
        const uint32_t bbase = sB_addr + stage * (STAGE_F * 4);
#pragma unroll
        for (int s = 0; s < 4; s++) {
            uint32_t af[4][4], bp[2][4];
#pragma unroll
            for (int mt = 0; mt < 4; mt++)
                ldsm_x4(af[mt], abase + aoff[mt] + s * 32);
#pragma unroll
            for (int p = 0; p < 2; p++)
                ldsm_x4(bp[p], bbase + boff[p] + s * 32);
#pragma unroll
            for (int mt = 0; mt < 4; mt++)
#pragma unroll
                for (int nt = 0; nt < 4; nt++)
                    mma_tf32(acc[mt][nt], af[mt], &bp[nt >> 1][(nt & 1) * 2]);
        }

        if (c + 1 < nchunk) {
            __syncthreads();
            const int ns = 1 - stage;
            float* da = stA + ns * STAGE_F;
            float* db = stB + ns * STAGE_F;
#pragma unroll
            for (int i = 0; i < 4; i++) {
                *(float4*)(da + i * 4) = make_float4(to_tf32(ra[i].x), to_tf32(ra[i].y),
                                                     to_tf32(ra[i].z), to_tf32(ra[i].w));
                *(float4*)(db + i * 4) = make_float4(to_tf32(rb[i].x), to_tf32(rb[i].y),
                                                     to_tf32(rb[i].z), to_tf32(rb[i].w));
            }
            __syncthreads();
        }
    }

    const int r0  = bm * 128 + warp_m * 64;
    const int c0g = bn * 128 + warp_n * 32;
#pragma unroll
    for (int n = 0; n < 4; n++) {
        const int col = c0g + n * 8 + 2 * lc;
        float2 bv = *(const float2*)(bias + col);
#pragma unroll
        for (int m = 0; m < 4; m++) {
            const int r = r0 + m * 16 + lr;
            float2 v0 = make_float2(acc[m][n][0] + bv.x, acc[m][n][1] + bv.y);
            float2 v1 = make_float2(acc[m][n][2] + bv.x, acc[m][n][3] + bv.y);
            if (relu) {
                v0.x = fmaxf(v0.x, 0.f); v0.y = fmaxf(v0.y, 0.f);
                v1.x = fmaxf(v1.x, 0.f); v1.y = fmaxf(v1.y, 0.f);
            }
            *(float2*)(C + (size_t)r * N + col)       = v0;
            *(float2*)(C + (size_t)(r + 8) * N + col) = v1;
        }
    }
}

// ============================================================================
// Tensor-core flash attention (R5, unchanged): 128x64 tiles, 8 warps.
// ============================================================================
#define KP 68
#define VP 72
#define PP 76
#define ATTN_SMEM ((64*KP + 64*VP + 128*PP) * 4)   // 74752 bytes

__global__ void __launch_bounds__(256, 2) attn_tc(
    const float* __restrict__ Q, const float* __restrict__ K,
    const float* __restrict__ V, const int* __restrict__ mask,
    float* __restrict__ O, int Skv, int causal)
{
    extern __shared__ float sm[];
    float* k_s = sm;                       // [64][KP]
    float* v_s = sm + 64 * KP;             // [64][VP]
    float* p_s = sm + 64 * KP + 64 * VP;   // [128][PP]

    const int t    = threadIdx.x;
    const int lane = t & 31;
    const int wid  = t >> 5;
    const int lr   = lane >> 2;
    const int lc   = lane & 3;
    const int wr0  = wid * 16;
    const int qt   = causal ? (gridDim.x - 1 - blockIdx.x) : blockIdx.x;
    const int h    = blockIdx.y;
    const int b    = blockIdx.z;
    const int qrow0 = qt * 128;

    const size_t qbase = ((size_t)(b * SEQ + qrow0)) * D_MODEL + h * DHEAD;

#pragma unroll
    for (int e = 0; e < 8; e++) {
        int f4 = e * 256 + t;
        int r = f4 >> 4, c4 = f4 & 15;
        float4 qv = *(const float4*)(Q + qbase + (size_t)r * D_MODEL + c4 * 4);
        float* dst = p_s + r * PP + c4 * 4;
        dst[0] = to_tf32(qv.x * 0.125f);
        dst[1] = to_tf32(qv.y * 0.125f);
        dst[2] = to_tf32(qv.z * 0.125f);
        dst[3] = to_tf32(qv.w * 0.125f);
    }
    __syncthreads();
    uint32_t qa[8][4];
#pragma unroll
    for (int kf = 0; kf < 8; kf++) {
        const float* qp = p_s + (wr0 + lr) * PP + kf * 8 + lc;
        qa[kf][0] = __float_as_uint(qp[0]);
        qa[kf][1] = __float_as_uint(qp[8 * PP]);
        qa[kf][2] = __float_as_uint(qp[4]);
        qa[kf][3] = __float_as_uint(qp[8 * PP + 4]);
    }

    float m_i[2] = {-1e30f, -1e30f};
    float l_i[2] = {0.f, 0.f};
    float oacc[8][4];
#pragma unroll
    for (int nf = 0; nf < 8; nf++)
#pragma unroll
        for (int e = 0; e < 4; e++) oacc[nf][e] = 0.f;

    const int r0g = qrow0 + wr0 + lr;
    const int ntiles = causal ? (2 * qt + 2) : (Skv >> 6);

    for (int jt = 0; jt < ntiles; jt++) {
        __syncthreads();
        const size_t kbase = ((size_t)(b * Skv + jt * 64)) * D_MODEL + h * DHEAD;
#pragma unroll
        for (int e = 0; e < 4; e++) {
            int f4 = e * 256 + t;
            int r = f4 >> 4, c4 = f4 & 15;
            float4 kv4 = *(const float4*)(K + kbase + (size_t)r * D_MODEL + c4 * 4);
            float4 vv4 = *(const float4*)(V + kbase + (size_t)r * D_MODEL + c4 * 4);
            float* kd = k_s + r * KP + c4 * 4;
            kd[0] = to_tf32(kv4.x); kd[1] = to_tf32(kv4.y);
            kd[2] = to_tf32(kv4.z); kd[3] = to_tf32(kv4.w);
            float* vd = v_s + r * VP + c4 * 4;
            vd[0] = to_tf32(vv4.x); vd[1] = to_tf32(vv4.y);
            vd[2] = to_tf32(vv4.z); vd[3] = to_tf32(vv4.w);
        }
        __syncthreads();

        float sacc[8][4];
#pragma unroll
        for (int nf = 0; nf < 8; nf++)
#pragma unroll
            for (int e = 0; e < 4; e++) sacc[nf][e] = 0.f;

#pragma unroll
        for (int ks = 0; ks < 8; ks++) {
#pragma unroll
            for (int nf = 0; nf < 8; nf++) {
                const float* kp = k_s + (nf * 8 + lr) * KP + ks * 8 + lc;
                uint32_t bf[2] = {__float_as_uint(kp[0]), __float_as_uint(kp[4])};
                mma_tf32(sacc[nf], qa[ks], bf);
            }
        }

        if (causal) {
            if (jt >= 2 * qt) {
#pragma unroll
                for (int nf = 0; nf < 8; nf++) {
                    int c0 = jt * 64 + nf * 8 + 2 * lc;
                    if (c0     > r0g)     sacc[nf][0] = -1e9f;
                    if (c0 + 1 > r0g)     sacc[nf][1] = -1e9f;
                    if (c0     > r0g + 8) sacc[nf][2] = -1e9f;
                    if (c0 + 1 > r0g + 8) sacc[nf][3] = -1e9f;
                }
            }
        } else {
            const int* mrow0 = mask + ((size_t)b * SEQ + r0g) * Skv + jt * 64;
            const int* mrow1 = mrow0 + 8 * Skv;
#pragma unroll
            for (int nf = 0; nf < 8; nf++) {
                int2 m0 = *(const int2*)(mrow0 + nf * 8 + 2 * lc);
                int2 m1 = *(const int2*)(mrow1 + nf * 8 + 2 * lc);
                if (!m0.x) sacc[nf][0] = -1e9f;
                if (!m0.y) sacc[nf][1] = -1e9f;
                if (!m1.x) sacc[nf][2] = -1e9f;
                if (!m1.y) sacc[nf][3] = -1e9f;
            }
        }

        float mx0 = -1e30f, mx1 = -1e30f;
#pragma unroll
        for (int nf = 0; nf < 8; nf++) {
            mx0 = fmaxf(mx0, fmaxf(sacc[nf][0], sacc[nf][1]));
            mx1 = fmaxf(mx1, fmaxf(sacc[nf][2], sacc[nf][3]));
        }
        mx0 = fmaxf(mx0, __shfl_xor_sync(0xffffffffu, mx0, 1));
        mx0 = fmaxf(mx0, __shfl_xor_sync(0xffffffffu, mx0, 2));
        mx1 = fmaxf(mx1, __shfl_xor_sync(0xffffffffu, mx1, 1));
        mx1 = fmaxf(mx1, __shfl_xor_sync(0xffffffffu, mx1, 2));
        float newm0 = fmaxf(m_i[0], mx0);
        float newm1 = fmaxf(m_i[1], mx1);
        float a0 = __expf(m_i[0] - newm0);
        float a1 = __expf(m_i[1] - newm1);
        m_i[0] = newm0; m_i[1] = newm1;

        float rs0 = 0.f, rs1 = 0.f;
#pragma unroll
        for (int nf = 0; nf < 8; nf++) {
            float p0 = __expf(sacc[nf][0] - newm0);
            float p1 = __expf(sacc[nf][1] - newm0);
            float p2 = __expf(sacc[nf][2] - newm1);
            float p3 = __expf(sacc[nf][3] - newm1);
            rs0 += p0 + p1;
            rs1 += p2 + p3;
            float* pr0 = p_s + (wr0 + lr) * PP + nf * 8 + 2 * lc;
            pr0[0] = to_tf32(p0); pr0[1] = to_tf32(p1);
            float* pr1 = pr0 + 8 * PP;
            pr1[0] = to_tf32(p2); pr1[1] = to_tf32(p3);
            oacc[nf][0] *= a0; oacc[nf][1] *= a0;
            oacc[nf][2] *= a1; oacc[nf][3] *= a1;
        }
        rs0 += __shfl_xor_sync(0xffffffffu, rs0, 1);
        rs0 += __shfl_xor_sync(0xffffffffu, rs0, 2);
        rs1 += __shfl_xor_sync(0xffffffffu, rs1, 1);
        rs1 += __shfl_xor_sync(0xffffffffu, rs1, 2);
        l_i[0] = l_i[0] * a0 + rs0;
        l_i[1] = l_i[1] * a1 + rs1;
        __syncwarp();

#pragma unroll
        for (int ks = 0; ks < 8; ks++) {
            const float* pp = p_s + (wr0 + lr) * PP + ks * 8 + lc;
            uint32_t af[4] = {__float_as_uint(pp[0]),
                              __float_as_uint(pp[8 * PP]),
                              __float_as_uint(pp[4]),
                              __float_as_uint(pp[8 * PP + 4])};
#pragma unroll
            for (int nf = 0; nf < 8; nf++) {
                const float* vp = v_s + (ks * 8 + lc) * VP + nf * 8 + lr;
                uint32_t bf[2] = {__float_as_uint(vp[0]),
                                  __float_as_uint(vp[4 * VP])};
                mma_tf32(oacc[nf], af, bf);
            }
        }
    }

    float inv0 = 1.f / l_i[0];
    float inv1 = 1.f / l_i[1];
#pragma unroll
    for (int nf = 0; nf < 8; nf++) {
        float* o0 = O + qbase + (size_t)(wr0 + lr) * D_MODEL + nf * 8 + 2 * lc;
        float* o1 = o0 + 8 * D_MODEL;
        *(float2*)o0 = make_float2(oacc[nf][0] * inv0, oacc[nf][1] * inv0);
        *(float2*)o1 = make_float2(oacc[nf][2] * inv1, oacc[nf][3] * inv1);
    }
}

// ---------------- fused residual add + LayerNorm ----------------------------
__global__ void __launch_bounds__(256) add_ln_kernel(
    const float* __restrict__ a, const float* __restrict__ r,
    const float* __restrict__ g, const float* __restrict__ be,
    float* __restrict__ out)
{
    const int row = blockIdx.x;
    const int t = threadIdx.x;
    const size_t base = (size_t)row * D_MODEL;

    float4 va = *(const float4*)(a + base + t * 4);
    float4 vr = *(const float4*)(r + base + t * 4);
    float v[4] = {va.x + vr.x, va.y + vr.y, va.z + vr.z, va.w + vr.w};

    float s = v[0] + v[1] + v[2] + v[3];
    float q = v[0]*v[0] + v[1]*v[1] + v[2]*v[2] + v[3]*v[3];
#pragma unroll
    for (int off = 16; off >= 1; off >>= 1) {
        s += __shfl_down_sync(0xffffffffu, s, off);
        q += __shfl_down_sync(0xffffffffu, q, off);
    }
    __shared__ float shs[8], shq[8], fin[2];
    int w = t >> 5, lane = t & 31;
    if (lane == 0) { shs[w] = s; shq[w] = q; }
    __syncthreads();
    if (t == 0) {
        float as = 0.f, aq = 0.f;
#pragma unroll
        for (int i = 0; i < 8; i++) { as += shs[i]; aq += shq[i]; }
        fin[0] = as; fin[1] = aq;
    }
    __syncthreads();
    float mu  = fin[0] * (1.f / D_MODEL);
    float var = fin[1] * (1.f / D_MODEL) - mu * mu;
    float rstd = rsqrtf(var + 1e-5f);

    float4 vg = *(const float4*)(g + t * 4);
    float4 vb = *(const float4*)(be + t * 4);
    float4 o;
    o.x = (v[0] - mu) * rstd * vg.x + vb.x;
    o.y = (v[1] - mu) * rstd * vg.y + vb.y;
    o.z = (v[2] - mu) * rstd * vg.z + vb.z;
    o.w = (v[3] - mu) * rstd * vg.w + vb.w;
    *(float4*)(out + base + t * 4) = o;
}

// ---------------- launch ----------------------------------------------------
static void run_gemm(const float* A, const float* W, const float* b, float* C,
                     int M, int N, int K, bool relu)
{
    dim3 grid(N / 128, M / 128);
    gemm_tc<<<grid, 256, GEMM_SMEM>>>(A, W, b, C, M, N, K, relu ? 1 : 0);
}

extern "C" void kernel_launch(void* const* d_in, const int* in_sizes, int n_in,
                              void* d_out, int out_size)
{
    (void)in_sizes; (void)n_in; (void)out_size;
    const float* x    = (const float*)d_in[0];
    const float* enc  = (const float*)d_in[1];
    const int* src_mask = (const int*)d_in[2];
    const int* tgt_mask = (const int*)d_in[3];
    const float* sa_Wq = (const float*)d_in[4];
    const float* sa_bq = (const float*)d_in[5];
    const float* sa_Wk = (const float*)d_in[6];
    const float* sa_bk = (const float*)d_in[7];
    const float* sa_Wv = (const float*)d_in[8];
    const float* sa_bv = (const float*)d_in[9];
    const float* sa_Wo = (const float*)d_in[10];
    const float* sa_bo = (const float*)d_in[11];
    const float* ca_Wq = (const float*)d_in[12];
    const float* ca_bq = (const float*)d_in[13];
    const float* ca_Wk = (const float*)d_in[14];
    const float* ca_bk = (const float*)d_in[15];
    const float* ca_Wv = (const float*)d_in[16];
    const float* ca_bv = (const float*)d_in[17];
    const float* ca_Wo = (const float*)d_in[18];
    const float* ca_bo = (const float*)d_in[19];
    const float* ff_W1 = (const float*)d_in[20];
    const float* ff_b1 = (const float*)d_in[21];
    const float* ff_W2 = (const float*)d_in[22];
    const float* ff_b2 = (const float*)d_in[23];
    const float* ln1_g = (const float*)d_in[24];
    const float* ln1_b = (const float*)d_in[25];
    const float* ln2_g = (const float*)d_in[26];
    const float* ln2_b = (const float*)d_in[27];
    const float* ln3_g = (const float*)d_in[28];
    const float* ln3_b = (const float*)d_in[29];
    float* out = (float*)d_out;

    float *q, *k, *v, *ctx, *tmp, *x1, *x2, *ff;
    cudaGetSymbolAddress((void**)&q,   g_q);
    cudaGetSymbolAddress((void**)&k,   g_k);
    cudaGetSymbolAddress((void**)&v,   g_v);
    cudaGetSymbolAddress((void**)&ctx, g_ctx);
    cudaGetSymbolAddress((void**)&tmp, g_tmp);
    cudaGetSymbolAddress((void**)&x1,  g_x1);
    cudaGetSymbolAddress((void**)&x2,  g_x2);
    cudaGetSymbolAddress((void**)&ff,  g_ff);

    cudaFuncSetAttribute(gemm_tc, cudaFuncAttributeMaxDynamicSharedMemorySize,
                         GEMM_SMEM);
    cudaFuncSetAttribute(attn_tc, cudaFuncAttributeMaxDynamicSharedMemorySize,
                         ATTN_SMEM);

    dim3 agrid(SEQ / 128, NHEAD, BATCH);

    // ---- self-attention ----
    run_gemm(x, sa_Wq, sa_bq, q, MROWS, D_MODEL, D_MODEL, false);
    run_gemm(x, sa_Wk, sa_bk, k, MROWS, D_MODEL, D_MODEL, false);
    run_gemm(x, sa_Wv, sa_bv, v, MROWS, D_MODEL, D_MODEL, false);
    attn_tc<<<agrid, 256, ATTN_SMEM>>>(q, k, v, tgt_mask, ctx, SEQ, 1);
    run_gemm(ctx, sa_Wo, sa_bo, tmp, MROWS, D_MODEL, D_MODEL, false);
    add_ln_kernel<<<MROWS, 256>>>(x, tmp, ln1_g, ln1_b, x1);

    // ---- cross-attention ----
    run_gemm(x1,  ca_Wq, ca_bq, q, MROWS, D_MODEL, D_MODEL, false);
    run_gemm(enc, ca_Wk, ca_bk, k, MROWS, D_MODEL, D_MODEL, false);
    run_gemm(enc, ca_Wv, ca_bv, v, MROWS, D_MODEL, D_MODEL, false);
    attn_tc<<<agrid, 256, ATTN_SMEM>>>(q, k, v, src_mask, ctx, SEQ, 0);
    run_gemm(ctx, ca_Wo, ca_bo, tmp, MROWS, D_MODEL, D_MODEL, false);
    add_ln_kernel<<<MROWS, 256>>>(x1, tmp, ln2_g, ln2_b, x2);

    // ---- feed-forward ----
    run_gemm(x2, ff_W1, ff_b1, ff, MROWS, DFF_SZ, D_MODEL, true);
    run_gemm(ff, ff_W2, ff_b2, tmp, MROWS, D_MODEL, DFF_SZ, false);
    add_ln_kernel<<<MROWS, 256>>>(x2, tmp, ln3_g, ln3_b, out);
}